// round 13
// baseline (speedup 1.0000x reference)
#include <cuda_runtime.h>
#include <cuda_bf16.h>

#define Bc 8
#define Nc 8192
#define Sc 1024
#define Kc 32
#define Pc (Bc*Sc*Kc)   // 262144 total grouped points

// ---------------- scratch (static device globals; no allocation) ----------------
__device__ float  g_h0[3*Pc];          // centered grouped coords, [c][P]
__device__ float  g_y1[64*Pc];         // 64 MiB
__device__ float  g_y2[64*Pc];         // 64 MiB
__device__ float  g_max3[Bc*Sc*128];   // per-centroid per-channel max of y3 (4 MiB)
__device__ float  g_min3[Bc*Sc*128];   // per-centroid per-channel min of y3 (4 MiB)
__device__ double g_sums[3][128][2];   // per-layer per-channel (sum, sumsq)
__device__ double g_m0[9];             // h0 moments: Sx,Sy,Sz,Sxx,Syy,Szz,Sxy,Sxz,Syz
__device__ float  g_stats[3][128][2];  // per-layer per-channel (scale, shift)

// ---------------- packed f32x2 pack helper ----------------
__device__ __forceinline__ unsigned long long pk2(float lo, float hi) {
    unsigned long long r; asm("mov.b64 %0, {%1, %2};" : "=l"(r) : "f"(lo), "f"(hi)); return r;
}

// Fused per-pair FPS update: ONE asm block, all temps internal. Exact semantics
// identical to the passing R7/R9/R12 path (unfused RN ops, same order).
__device__ __forceinline__ void upd2(unsigned long long X, unsigned long long Y, unsigned long long Z,
                                     unsigned long long NX, unsigned long long NY, unsigned long long NZ,
                                     float& d0, float& d1, float& m) {
    asm("{\n\t"
        ".reg .b64 dx, dy, dz, tx, ty, tz, s;\n\t"
        ".reg .f32 lo, hi;\n\t"
        "add.rn.f32x2 dx, %3, %6;\n\t"
        "add.rn.f32x2 dy, %4, %7;\n\t"
        "add.rn.f32x2 dz, %5, %8;\n\t"
        "mul.rn.f32x2 tx, dx, dx;\n\t"
        "mul.rn.f32x2 ty, dy, dy;\n\t"
        "mul.rn.f32x2 tz, dz, dz;\n\t"
        "add.rn.f32x2 s, tx, ty;\n\t"
        "add.rn.f32x2 s, s, tz;\n\t"
        "mov.b64 {lo, hi}, s;\n\t"
        "min.f32 %0, %0, lo;\n\t"
        "min.f32 %1, %1, hi;\n\t"
        "max.f32 %2, %2, %0;\n\t"
        "max.f32 %2, %2, %1;\n\t"
        "}"
        : "+f"(d0), "+f"(d1), "+f"(m)
        : "l"(X), "l"(Y), "l"(Z), "l"(NX), "l"(NY), "l"(NZ));
}

// ---------------- FPS v8: exact spatial pruning, warp + HALF granularity ----------------
// Counting-sort by 4x4x4 Morton cell (init). Warp owns 512 sorted points; its two
// 256-point halves get their own bboxes. Skip warp (or a half) when the centroid's
// conservative box distance >= U = warp's current max dd: then min(dd,d)==dd for all
// covered points, so dd stays bit-exact. Cached per-half dd maxes (hm0/hm1) let m be
// rebuilt without touching skipped halves. Tie-break = exact lowest ORIGINAL index.
__global__ void __launch_bounds__(512, 1)
fps_kernel(const float* __restrict__ x, float* __restrict__ out_newx) {
    extern __shared__ float sm[];
    float* sx = sm;
    float* sy = sm + Nc;
    float* sz = sm + 2*Nc;
    int*   spidx = (int*)(sm + 3*Nc);                      // sorted orig indices
    unsigned long long* swb = (unsigned long long*)(spidx + Nc);  // [2][16] parity bufs
    __shared__ int s_cnt[64];

    int b = blockIdx.x, tid = threadIdx.x;
    int lane = tid & 31, wid = tid >> 5;
    const float* xb = x + (size_t)b*Nc*3;

    for (int i = tid; i < Nc; i += 512) {
        sx[i] = xb[i*3+0];
        sy[i] = xb[i*3+1];
        sz[i] = xb[i*3+2];
    }
    if (tid < 64) s_cnt[tid] = 0;
    __syncthreads();

    // ---- counting sort by Morton cell (init only) ----
    int rank16[16]; int cid16[16];
#pragma unroll
    for (int t = 0; t < 16; t++) {
        int i = tid + t*512;
        int ix = min((int)(sx[i]*4.f), 3);
        int iy = min((int)(sy[i]*4.f), 3);
        int iz = min((int)(sz[i]*4.f), 3);
        int cid = (ix&1) | ((iy&1)<<1) | ((iz&1)<<2)
                | ((ix>>1)<<3) | ((iy>>1)<<4) | ((iz>>1)<<5);
        cid16[t] = cid;
        rank16[t] = atomicAdd(&s_cnt[cid], 1);
    }
    __syncthreads();
    if (tid == 0) {
        int acc = 0;
#pragma unroll
        for (int c = 0; c < 64; c++) { int v = s_cnt[c]; s_cnt[c] = acc; acc += v; }
    }
    __syncthreads();
#pragma unroll
    for (int t = 0; t < 16; t++)
        spidx[s_cnt[cid16[t]] + rank16[t]] = tid + t*512;
    __syncthreads();

    // ---- register load + per-half bboxes ----
    unsigned long long Xr[8], Yr[8], Zr[8];
    unsigned oi[8];
    float hb[2][6];   // [half][x0,x1,y0,y1,z0,z1]
#pragma unroll
    for (int h = 0; h < 2; h++) {
        float lx0 = 1e30f, lx1 = -1e30f, ly0 = 1e30f, ly1 = -1e30f, lz0 = 1e30f, lz1 = -1e30f;
#pragma unroll
        for (int kk = 0; kk < 4; kk++) {
            int k = h*4 + kk;
            int pos = wid*512 + k*64 + lane*2;
            int i0 = spidx[pos], i1 = spidx[pos+1];
            float x0 = sx[i0], x1 = sx[i1];
            float y0 = sy[i0], y1 = sy[i1];
            float z0 = sz[i0], z1 = sz[i1];
            Xr[k] = pk2(x0, x1); Yr[k] = pk2(y0, y1); Zr[k] = pk2(z0, z1);
            oi[k] = (unsigned)i0 | ((unsigned)i1 << 16);
            lx0 = fminf(lx0, fminf(x0, x1)); lx1 = fmaxf(lx1, fmaxf(x0, x1));
            ly0 = fminf(ly0, fminf(y0, y1)); ly1 = fmaxf(ly1, fmaxf(y0, y1));
            lz0 = fminf(lz0, fminf(z0, z1)); lz1 = fmaxf(lz1, fmaxf(z0, z1));
        }
        // coords >= 0 -> uint order == float order
        hb[h][0] = __uint_as_float(__reduce_min_sync(0xffffffffu, __float_as_uint(lx0)));
        hb[h][1] = __uint_as_float(__reduce_max_sync(0xffffffffu, __float_as_uint(lx1)));
        hb[h][2] = __uint_as_float(__reduce_min_sync(0xffffffffu, __float_as_uint(ly0)));
        hb[h][3] = __uint_as_float(__reduce_max_sync(0xffffffffu, __float_as_uint(ly1)));
        hb[h][4] = __uint_as_float(__reduce_min_sync(0xffffffffu, __float_as_uint(lz0)));
        hb[h][5] = __uint_as_float(__reduce_max_sync(0xffffffffu, __float_as_uint(lz1)));
    }
    float wb0 = fminf(hb[0][0], hb[1][0]), wb1 = fmaxf(hb[0][1], hb[1][1]);
    float wb2 = fminf(hb[0][2], hb[1][2]), wb3 = fmaxf(hb[0][3], hb[1][3]);
    float wb4 = fminf(hb[0][4], hb[1][4]), wb5 = fmaxf(hb[0][5], hb[1][5]);

    float dd[16];
#pragma unroll
    for (int i = 0; i < 16; i++) dd[i] = 1e10f;
    float hm0 = 1e10f, hm1 = 1e10f;     // cached per-half dd maxes

    unsigned long long kcache = 0x7F800000ULL << 32;   // U = +inf -> first iter updates

    int far = 0;
    for (int it = 0; it < Sc; ++it) {
        float cx = sx[far], cy = sy[far], cz = sz[far];
        if (tid == 0) {
            float* o = &out_newx[((size_t)b*Sc + it)*3];
            o[0] = cx; o[1] = cy; o[2] = cz;
        }
        float U = __uint_as_float((unsigned)(kcache >> 32));

        // warp-level conservative box test
        float tx = fmaxf(fmaxf(wb0 - cx, cx - wb1), 0.f);
        float ty = fmaxf(fmaxf(wb2 - cy, cy - wb3), 0.f);
        float tz = fmaxf(fmaxf(wb4 - cz, cz - wb5), 0.f);
        float d2w = fmaf(tx, tx, fmaf(ty, ty, tz*tz));

        if (!(d2w * 0.999997f >= U)) {
            unsigned long long NX = pk2(-cx, -cx), NY = pk2(-cy, -cy), NZ = pk2(-cz, -cz);
            bool upd = false;

            // half 0
            {
                float ax = fmaxf(fmaxf(hb[0][0] - cx, cx - hb[0][1]), 0.f);
                float ay = fmaxf(fmaxf(hb[0][2] - cy, cy - hb[0][3]), 0.f);
                float az = fmaxf(fmaxf(hb[0][4] - cz, cz - hb[0][5]), 0.f);
                float d2h = fmaf(ax, ax, fmaf(ay, ay, az*az));
                if (!(d2h * 0.999997f >= U)) {
                    hm0 = -1.f;
#pragma unroll
                    for (int k = 0; k < 4; k++)
                        upd2(Xr[k], Yr[k], Zr[k], NX, NY, NZ, dd[2*k], dd[2*k+1], hm0);
                    upd = true;
                }
            }
            // half 1
            {
                float ax = fmaxf(fmaxf(hb[1][0] - cx, cx - hb[1][1]), 0.f);
                float ay = fmaxf(fmaxf(hb[1][2] - cy, cy - hb[1][3]), 0.f);
                float az = fmaxf(fmaxf(hb[1][4] - cz, cz - hb[1][5]), 0.f);
                float d2h = fmaf(ax, ax, fmaf(ay, ay, az*az));
                if (!(d2h * 0.999997f >= U)) {
                    hm1 = -1.f;
#pragma unroll
                    for (int k = 4; k < 8; k++)
                        upd2(Xr[k], Yr[k], Zr[k], NX, NY, NZ, dd[2*k], dd[2*k+1], hm1);
                    upd = true;
                }
            }

            if (upd) {
                float m = fmaxf(hm0, hm1);
                unsigned wmax = __reduce_max_sync(0xffffffffu, __float_as_uint(m));
                unsigned cand = 0xFFFFFFFFu;
#pragma unroll
                for (int k = 0; k < 8; k++) {
                    if (__float_as_uint(dd[2*k])   == wmax) cand = min(cand, oi[k] & 0xFFFFu);
                    if (__float_as_uint(dd[2*k+1]) == wmax) cand = min(cand, oi[k] >> 16);
                }
                unsigned wc = __reduce_min_sync(0xffffffffu, cand);
                kcache = ((unsigned long long)wmax << 32) | (unsigned)(Nc - 1 - wc);
            }
        }

        unsigned long long* buf = swb + (it & 1)*16;
        if (lane == 0) buf[wid] = kcache;
        __syncthreads();

        unsigned long long e = buf[lane & 15];
        unsigned hi = (unsigned)(e >> 32);
        unsigned lo = (unsigned)(e & 0xFFFFFFFFull);
        unsigned M  = __reduce_max_sync(0xffffffffu, hi);
        unsigned r  = __reduce_max_sync(0xffffffffu, (hi == M) ? lo : 0u);
        far = Nc - 1 - (int)r;
    }
}

// ---------------- ball query + group + center + h0 moment accumulation ----------------
__global__ void ball_kernel(const float* __restrict__ x, const float* __restrict__ newx) {
    __shared__ double sm9[9];
    int tid = threadIdx.x;
    if (tid < 9) sm9[tid] = 0.0;
    __syncthreads();

    int gw   = (blockIdx.x * blockDim.x + tid) >> 5;
    int lane = tid & 31;
    int b = gw >> 10;
    const float* xb = x + (size_t)b*Nc*3;

    float cx = newx[gw*3+0], cy = newx[gw*3+1], cz = newx[gw*3+2];
    float c2 = __fadd_rn(__fadd_rn(__fmul_rn(cx,cx), __fmul_rn(cy,cy)), __fmul_rn(cz,cz));

    int cnt = 0, firstIdx = -1;
    int pb = gw * Kc;
    float m1 = 0.f, m2 = 0.f, m3 = 0.f, m4 = 0.f, m5 = 0.f, m6 = 0.f, m7 = 0.f, m8 = 0.f, m9 = 0.f;

    for (int base = 0; base < Nc && cnt < Kc; base += 32) {
        int j = base + lane;
        float ax = xb[j*3+0], ay = xb[j*3+1], az = xb[j*3+2];
        float dot = __fadd_rn(__fadd_rn(__fmul_rn(cx,ax), __fmul_rn(cy,ay)), __fmul_rn(cz,az));
        float p2  = __fadd_rn(__fadd_rn(__fmul_rn(ax,ax), __fmul_rn(ay,ay)), __fmul_rn(az,az));
        float sq  = __fadd_rn(__fadd_rn(__fmul_rn(-2.0f, dot), c2), p2);
        bool in = !(sq > 0.04f);

        unsigned m = __ballot_sync(0xffffffffu, in);
        int pos = cnt + __popc(m & ((1u << lane) - 1u));
        if (in && pos < Kc) {
            float hx = ax - cx, hy = ay - cy, hz = az - cz;
            g_h0[pb + pos]        = hx;
            g_h0[Pc + pb + pos]   = hy;
            g_h0[2*Pc + pb + pos] = hz;
            m1 += hx; m2 += hy; m3 += hz;
            m4 += hx*hx; m5 += hy*hy; m6 += hz*hz;
            m7 += hx*hy; m8 += hx*hz; m9 += hy*hz;
        }
        if (firstIdx < 0 && m) firstIdx = base + __ffs(m) - 1;
        cnt += __popc(m);
    }
    cnt = min(cnt, Kc);
    if (lane >= cnt && firstIdx >= 0) {
        float ax = xb[firstIdx*3+0], ay = xb[firstIdx*3+1], az = xb[firstIdx*3+2];
        float hx = ax - cx, hy = ay - cy, hz = az - cz;
        g_h0[pb + lane]        = hx;
        g_h0[Pc + pb + lane]   = hy;
        g_h0[2*Pc + pb + lane] = hz;
        m1 += hx; m2 += hy; m3 += hz;
        m4 += hx*hx; m5 += hy*hy; m6 += hz*hz;
        m7 += hx*hy; m8 += hx*hz; m9 += hy*hz;
    }
    // warp reduce 9 moments then one lane adds to block bins
#pragma unroll
    for (int off = 16; off; off >>= 1) {
        m1 += __shfl_xor_sync(0xffffffffu, m1, off);
        m2 += __shfl_xor_sync(0xffffffffu, m2, off);
        m3 += __shfl_xor_sync(0xffffffffu, m3, off);
        m4 += __shfl_xor_sync(0xffffffffu, m4, off);
        m5 += __shfl_xor_sync(0xffffffffu, m5, off);
        m6 += __shfl_xor_sync(0xffffffffu, m6, off);
        m7 += __shfl_xor_sync(0xffffffffu, m7, off);
        m8 += __shfl_xor_sync(0xffffffffu, m8, off);
        m9 += __shfl_xor_sync(0xffffffffu, m9, off);
    }
    if (lane == 0) {
        atomicAdd(&sm9[0], (double)m1); atomicAdd(&sm9[1], (double)m2);
        atomicAdd(&sm9[2], (double)m3); atomicAdd(&sm9[3], (double)m4);
        atomicAdd(&sm9[4], (double)m5); atomicAdd(&sm9[5], (double)m6);
        atomicAdd(&sm9[6], (double)m7); atomicAdd(&sm9[7], (double)m8);
        atomicAdd(&sm9[8], (double)m9);
    }
    __syncthreads();
    if (tid < 9) atomicAdd(&g_m0[tid], sm9[tid]);
}

// ---------------- layer 1: 3 -> 64 ----------------
__global__ void layer1_kernel(const float* __restrict__ W, const float* __restrict__ bb) {
    __shared__ float sW[64*3], sb[64];
    int tid = threadIdx.x;
    if (tid < 192) sW[tid] = W[tid];
    if (tid < 64)  sb[tid] = bb[tid];
    __syncthreads();

    int p = blockIdx.x * 256 + tid;
    float h0 = g_h0[p], h1 = g_h0[Pc + p], h2 = g_h0[2*Pc + p];
#pragma unroll
    for (int o = 0; o < 64; o++) {
        float y = fmaf(sW[o*3+2], h2, fmaf(sW[o*3+1], h1, fmaf(sW[o*3+0], h0, sb[o])));
        g_y1[(size_t)o*Pc + p] = y;
    }
}

// ---------------- init sums ----------------
__global__ void init_sums_kernel() {
    int i = threadIdx.x;
    if (i < 3*128*2) ((double*)g_sums)[i] = 0.0;
    if (i < 9) g_m0[i] = 0.0;
}

// ---------------- finalize layer0 stats from h0 moments (analytic) ----------------
__global__ void finalize0_kernel(const float* __restrict__ W, const float* __restrict__ bb,
                                 const float* __restrict__ g, const float* __restrict__ be) {
    int c = threadIdx.x;
    if (c < 64) {
        double n = (double)Pc;
        double mu[3]  = { g_m0[0]/n, g_m0[1]/n, g_m0[2]/n };
        double M[3][3];
        M[0][0] = g_m0[3]/n; M[1][1] = g_m0[4]/n; M[2][2] = g_m0[5]/n;
        M[0][1] = M[1][0] = g_m0[6]/n;
        M[0][2] = M[2][0] = g_m0[7]/n;
        M[1][2] = M[2][1] = g_m0[8]/n;
        double w0 = (double)W[c*3+0], w1 = (double)W[c*3+1], w2 = (double)W[c*3+2];
        double bv = (double)bb[c];
        double mean = w0*mu[0] + w1*mu[1] + w2*mu[2] + bv;
        double ey2 = w0*w0*M[0][0] + w1*w1*M[1][1] + w2*w2*M[2][2]
                   + 2.0*(w0*w1*M[0][1] + w0*w2*M[0][2] + w1*w2*M[1][2])
                   + 2.0*bv*(w0*mu[0] + w1*mu[1] + w2*mu[2]) + bv*bv;
        double var = ey2 - mean*mean;
        float invstd = (float)rsqrt(var + 1e-5);
        float scale = g[c] * invstd;
        float shift = fmaf(-(float)mean, scale, be[c]);
        g_stats[0][c][0] = scale;
        g_stats[0][c][1] = shift;
    }
}

// ---------------- fold BN into scale/shift (layers 1,2) ----------------
__global__ void finalize_kernel(int layer, int C, const float* __restrict__ g, const float* __restrict__ be) {
    int c = threadIdx.x;
    if (c < C) {
        double n = (double)Pc;
        double mean = g_sums[layer][c][0] / n;
        double var  = g_sums[layer][c][1] / n - mean*mean;
        float invstd = (float)rsqrt(var + 1e-5);
        float scale = g[c] * invstd;
        float shift = fmaf(-(float)mean, scale, be[c]);
        g_stats[layer][c][0] = scale;
        g_stats[layer][c][1] = shift;
    }
}

// ---------------- layer 2: 64 -> 64 (norm+ReLU of y1 on the fly) + fused stats ----------------
__global__ void layer2_kernel(const float* __restrict__ W, const float* __restrict__ bb) {
    __shared__ float sW[64*64];      // [c][o]
    __shared__ float sb[64], ssc[64], ssh[64];
    __shared__ double sSum[64], sSq[64];
    int tid = threadIdx.x, lane = tid & 31;
    for (int i = tid; i < 4096; i += 256) {
        int c = i >> 6, o = i & 63;
        sW[i] = W[o*64 + c];
    }
    if (tid < 64) {
        sb[tid]  = bb[tid];
        ssc[tid] = g_stats[0][tid][0];
        ssh[tid] = g_stats[0][tid][1];
        sSum[tid] = 0.0; sSq[tid] = 0.0;
    }
    __syncthreads();

    int p = blockIdx.x * 256 + tid;
    float acc[64];
#pragma unroll
    for (int o = 0; o < 64; o++) acc[o] = sb[o];

    for (int c = 0; c < 64; c++) {
        float v = g_y1[(size_t)c*Pc + p];
        float h = fmaxf(fmaf(v, ssc[c], ssh[c]), 0.f);
        const float4* wr = (const float4*)(sW + c*64);
#pragma unroll
        for (int o4 = 0; o4 < 16; o4++) {
            float4 w = wr[o4];
            acc[o4*4+0] = fmaf(w.x, h, acc[o4*4+0]);
            acc[o4*4+1] = fmaf(w.y, h, acc[o4*4+1]);
            acc[o4*4+2] = fmaf(w.z, h, acc[o4*4+2]);
            acc[o4*4+3] = fmaf(w.w, h, acc[o4*4+3]);
        }
    }
#pragma unroll
    for (int o = 0; o < 64; o++) g_y2[(size_t)o*Pc + p] = acc[o];

    // fused stats: per-channel sum/sumsq
    double ksm0 = 0.0, ksm1 = 0.0, ksq0 = 0.0, ksq1 = 0.0;
#pragma unroll 4
    for (int o = 0; o < 64; o++) {
        float v = acc[o];
        float s1 = v, s2 = v*v;
#pragma unroll
        for (int off = 16; off; off >>= 1) {
            s1 += __shfl_xor_sync(0xffffffffu, s1, off);
            s2 += __shfl_xor_sync(0xffffffffu, s2, off);
        }
        if (o == 2*lane)     { ksm0 = (double)s1; ksq0 = (double)s2; }
        if (o == 2*lane + 1) { ksm1 = (double)s1; ksq1 = (double)s2; }
    }
    atomicAdd(&sSum[2*lane],   ksm0);
    atomicAdd(&sSum[2*lane+1], ksm1);
    atomicAdd(&sSq[2*lane],    ksq0);
    atomicAdd(&sSq[2*lane+1],  ksq1);
    __syncthreads();
    if (tid < 64) {
        atomicAdd(&g_sums[1][tid][0], sSum[tid]);
        atomicAdd(&g_sums[1][tid][1], sSq[tid]);
    }
}

// ---------------- layer 3 fused: 64 -> 128, per-centroid max/min + global stats ----------------
__global__ void layer3_kernel(const float* __restrict__ W, const float* __restrict__ bb) {
    int half = blockIdx.y;
    __shared__ float sW[64*64];
    __shared__ float sb[64], ssc[64], ssh[64];
    __shared__ double sSum[64], sSq[64];
    int tid = threadIdx.x, lane = tid & 31;
    for (int i = tid; i < 4096; i += 256) {
        int c = i >> 6, oo = i & 63;
        sW[i] = W[(half*64 + oo)*64 + c];
    }
    if (tid < 64) {
        sb[tid]  = bb[half*64 + tid];
        ssc[tid] = g_stats[1][tid][0];
        ssh[tid] = g_stats[1][tid][1];
        sSum[tid] = 0.0; sSq[tid] = 0.0;
    }
    __syncthreads();

    int p = blockIdx.x * 256 + tid;
    float acc[64];
#pragma unroll
    for (int o = 0; o < 64; o++) acc[o] = sb[o];

    for (int c = 0; c < 64; c++) {
        float v = g_y2[(size_t)c*Pc + p];
        float h = fmaxf(fmaf(v, ssc[c], ssh[c]), 0.f);
        const float4* wr = (const float4*)(sW + c*64);
#pragma unroll
        for (int o4 = 0; o4 < 16; o4++) {
            float4 w = wr[o4];
            acc[o4*4+0] = fmaf(w.x, h, acc[o4*4+0]);
            acc[o4*4+1] = fmaf(w.y, h, acc[o4*4+1]);
            acc[o4*4+2] = fmaf(w.z, h, acc[o4*4+2]);
            acc[o4*4+3] = fmaf(w.w, h, acc[o4*4+3]);
        }
    }

    int cent = p >> 5;
    float kmx0 = 0.f, kmx1 = 0.f, kmn0 = 0.f, kmn1 = 0.f;
    double ksm0 = 0.0, ksm1 = 0.0, ksq0 = 0.0, ksq1 = 0.0;
#pragma unroll 4
    for (int o = 0; o < 64; o++) {
        float v = acc[o];
        float mx = v, mn = v, s1 = v, s2 = v*v;
#pragma unroll
        for (int off = 16; off; off >>= 1) {
            mx = fmaxf(mx, __shfl_xor_sync(0xffffffffu, mx, off));
            mn = fminf(mn, __shfl_xor_sync(0xffffffffu, mn, off));
            s1 += __shfl_xor_sync(0xffffffffu, s1, off);
            s2 += __shfl_xor_sync(0xffffffffu, s2, off);
        }
        if (o == 2*lane)     { kmx0 = mx; kmn0 = mn; ksm0 = (double)s1; ksq0 = (double)s2; }
        if (o == 2*lane + 1) { kmx1 = mx; kmn1 = mn; ksm1 = (double)s1; ksq1 = (double)s2; }
    }
    size_t base = (size_t)cent*128 + half*64 + 2*lane;
    *(float2*)&g_max3[base] = make_float2(kmx0, kmx1);
    *(float2*)&g_min3[base] = make_float2(kmn0, kmn1);

    atomicAdd(&sSum[2*lane],   ksm0);
    atomicAdd(&sSum[2*lane+1], ksm1);
    atomicAdd(&sSq[2*lane],    ksq0);
    atomicAdd(&sSq[2*lane+1],  ksq1);
    __syncthreads();
    if (tid < 64) {
        atomicAdd(&g_sums[2][half*64 + tid][0], sSum[tid]);
        atomicAdd(&g_sums[2][half*64 + tid][1], sSq[tid]);
    }
}

// ---------------- final: affine + ReLU on pre-pooled extremes ----------------
__global__ void final_kernel(float* __restrict__ outf) {
    int bs = blockIdx.x;
    int o  = threadIdx.x;
    float sc = g_stats[2][o][0], sh = g_stats[2][o][1];
    float v = (sc >= 0.f) ? g_max3[(size_t)bs*128 + o] : g_min3[(size_t)bs*128 + o];
    outf[(size_t)bs*128 + o] = fmaxf(fmaf(v, sc, sh), 0.f);
}

// ---------------- launch ----------------
extern "C" void kernel_launch(void* const* d_in, const int* in_sizes, int n_in,
                              void* d_out, int out_size) {
    const float* x   = (const float*)d_in[0];
    const float* W1  = (const float*)d_in[1];
    const float* b1  = (const float*)d_in[2];
    const float* g1  = (const float*)d_in[3];
    const float* be1 = (const float*)d_in[4];
    const float* W2  = (const float*)d_in[5];
    const float* b2  = (const float*)d_in[6];
    const float* g2  = (const float*)d_in[7];
    const float* be2 = (const float*)d_in[8];
    const float* W3  = (const float*)d_in[9];
    const float* b3  = (const float*)d_in[10];
    const float* g3  = (const float*)d_in[11];
    const float* be3 = (const float*)d_in[12];

    float* out  = (float*)d_out;            // new_x: 8*1024*3
    float* outF = out + Bc*Sc*3;            // features: 8*1024*128

    // 3*Nc coords + Nc sorted-index ints + 2*16 u64 parity buffers
    size_t fps_smem = (size_t)(3*Nc)*sizeof(float) + (size_t)Nc*sizeof(int)
                    + 32*sizeof(unsigned long long);
    cudaFuncSetAttribute(fps_kernel, cudaFuncAttributeMaxDynamicSharedMemorySize, (int)fps_smem);

    fps_kernel<<<Bc, 512, fps_smem>>>(x, out);
    init_sums_kernel<<<1, 1024>>>();
    ball_kernel<<<(Bc*Sc*32)/256, 256>>>(x, out);

    layer1_kernel<<<Pc/256, 256>>>(W1, b1);
    finalize0_kernel<<<1, 64>>>(W1, b1, g1, be1);

    layer2_kernel<<<Pc/256, 256>>>(W2, b2);
    finalize_kernel<<<1, 128>>>(1, 64, g2, be2);

    layer3_kernel<<<dim3(Pc/256, 2), 256>>>(W3, b3);
    finalize_kernel<<<1, 128>>>(2, 128, g3, be3);

    final_kernel<<<Bc*Sc, 128>>>(outF);
}

// round 14
// speedup vs baseline: 1.0936x; 1.0936x over previous
#include <cuda_runtime.h>
#include <cuda_bf16.h>

#define Bc 8
#define Nc 8192
#define Sc 1024
#define Kc 32
#define Pc (Bc*Sc*Kc)   // 262144 total grouped points

// ---------------- scratch (static device globals; no allocation) ----------------
__device__ float  g_h0[3*Pc];          // centered grouped coords, [c][P]
__device__ float  g_y1[64*Pc];         // 64 MiB
__device__ float  g_y2[64*Pc];         // 64 MiB
__device__ float  g_max3[Bc*Sc*128];   // per-centroid per-channel max of y3 (4 MiB)
__device__ float  g_min3[Bc*Sc*128];   // per-centroid per-channel min of y3 (4 MiB)
__device__ double g_sums[3][128][2];   // per-layer per-channel (sum, sumsq)
__device__ double g_m0[9];             // h0 moments: Sx,Sy,Sz,Sxx,Syy,Szz,Sxy,Sxz,Syz
__device__ float  g_stats[3][128][2];  // per-layer per-channel (scale, shift)

// ---------------- packed f32x2 pack helper ----------------
__device__ __forceinline__ unsigned long long pk2(float lo, float hi) {
    unsigned long long r; asm("mov.b64 %0, {%1, %2};" : "=l"(r) : "f"(lo), "f"(hi)); return r;
}

// Fused per-pair FPS update: ONE asm block, all temps internal. Exact semantics
// identical to the passing R7/R9/R12 path (unfused RN ops, same order).
__device__ __forceinline__ void upd2(unsigned long long X, unsigned long long Y, unsigned long long Z,
                                     unsigned long long NX, unsigned long long NY, unsigned long long NZ,
                                     float& d0, float& d1, float& m) {
    asm("{\n\t"
        ".reg .b64 dx, dy, dz, tx, ty, tz, s;\n\t"
        ".reg .f32 lo, hi;\n\t"
        "add.rn.f32x2 dx, %3, %6;\n\t"
        "add.rn.f32x2 dy, %4, %7;\n\t"
        "add.rn.f32x2 dz, %5, %8;\n\t"
        "mul.rn.f32x2 tx, dx, dx;\n\t"
        "mul.rn.f32x2 ty, dy, dy;\n\t"
        "mul.rn.f32x2 tz, dz, dz;\n\t"
        "add.rn.f32x2 s, tx, ty;\n\t"
        "add.rn.f32x2 s, s, tz;\n\t"
        "mov.b64 {lo, hi}, s;\n\t"
        "min.f32 %0, %0, lo;\n\t"
        "min.f32 %1, %1, hi;\n\t"
        "max.f32 %2, %2, %0;\n\t"
        "max.f32 %2, %2, %1;\n\t"
        "}"
        : "+f"(d0), "+f"(d1), "+f"(m)
        : "l"(X), "l"(Y), "l"(Z), "l"(NX), "l"(NY), "l"(NZ));
}

// ---------------- FPS v7 (R12-proven): exact warp-level spatial pruning ----------------
// Points counting-sorted by 4x4x4 Morton cell (init, smem). Warp w owns sorted
// positions [512w, 512w+512). Per iteration a warp SKIPS the distance update when
// dmin(c, warp bbox)^2 (with conservative margin) >= U = warp's current max dd:
// min(dd, d(p,c)) == dd provably for all its points, so dd and the cached key stay
// bit-exact. Tie-break = exact lowest ORIGINAL index among max-dd points.
__global__ void __launch_bounds__(512, 1)
fps_kernel(const float* __restrict__ x, float* __restrict__ out_newx) {
    extern __shared__ float sm[];
    float* sx = sm;
    float* sy = sm + Nc;
    float* sz = sm + 2*Nc;
    int*   spidx = (int*)(sm + 3*Nc);                      // sorted orig indices
    unsigned long long* swb = (unsigned long long*)(spidx + Nc);  // [2][16] parity bufs
    __shared__ int s_cnt[64];

    int b = blockIdx.x, tid = threadIdx.x;
    int lane = tid & 31, wid = tid >> 5;
    const float* xb = x + (size_t)b*Nc*3;

    for (int i = tid; i < Nc; i += 512) {
        sx[i] = xb[i*3+0];
        sy[i] = xb[i*3+1];
        sz[i] = xb[i*3+2];
    }
    if (tid < 64) s_cnt[tid] = 0;
    __syncthreads();

    // ---- counting sort by Morton cell (init only) ----
    int rank16[16]; int cid16[16];
#pragma unroll
    for (int t = 0; t < 16; t++) {
        int i = tid + t*512;
        int ix = min((int)(sx[i]*4.f), 3);
        int iy = min((int)(sy[i]*4.f), 3);
        int iz = min((int)(sz[i]*4.f), 3);
        int cid = (ix&1) | ((iy&1)<<1) | ((iz&1)<<2)
                | ((ix>>1)<<3) | ((iy>>1)<<4) | ((iz>>1)<<5);
        cid16[t] = cid;
        rank16[t] = atomicAdd(&s_cnt[cid], 1);
    }
    __syncthreads();
    if (tid == 0) {
        int acc = 0;
#pragma unroll
        for (int c = 0; c < 64; c++) { int v = s_cnt[c]; s_cnt[c] = acc; acc += v; }
    }
    __syncthreads();
#pragma unroll
    for (int t = 0; t < 16; t++)
        spidx[s_cnt[cid16[t]] + rank16[t]] = tid + t*512;
    __syncthreads();

    // ---- register load (16 pts/thread via sorted indices) + warp bbox ----
    unsigned long long Xr[8], Yr[8], Zr[8];
    unsigned oi[8];            // two 16-bit orig indices per pair
    float lx0 = 1e30f, lx1 = -1e30f, ly0 = 1e30f, ly1 = -1e30f, lz0 = 1e30f, lz1 = -1e30f;
#pragma unroll
    for (int k = 0; k < 8; k++) {
        int pos = wid*512 + k*64 + lane*2;
        int i0 = spidx[pos], i1 = spidx[pos+1];
        float x0 = sx[i0], x1 = sx[i1];
        float y0 = sy[i0], y1 = sy[i1];
        float z0 = sz[i0], z1 = sz[i1];
        Xr[k] = pk2(x0, x1); Yr[k] = pk2(y0, y1); Zr[k] = pk2(z0, z1);
        oi[k] = (unsigned)i0 | ((unsigned)i1 << 16);
        lx0 = fminf(lx0, fminf(x0, x1)); lx1 = fmaxf(lx1, fmaxf(x0, x1));
        ly0 = fminf(ly0, fminf(y0, y1)); ly1 = fmaxf(ly1, fmaxf(y0, y1));
        lz0 = fminf(lz0, fminf(z0, z1)); lz1 = fmaxf(lz1, fmaxf(z0, z1));
    }
    // coords >= 0 -> uint order == float order
    float bx0 = __uint_as_float(__reduce_min_sync(0xffffffffu, __float_as_uint(lx0)));
    float bx1 = __uint_as_float(__reduce_max_sync(0xffffffffu, __float_as_uint(lx1)));
    float by0 = __uint_as_float(__reduce_min_sync(0xffffffffu, __float_as_uint(ly0)));
    float by1 = __uint_as_float(__reduce_max_sync(0xffffffffu, __float_as_uint(ly1)));
    float bz0 = __uint_as_float(__reduce_min_sync(0xffffffffu, __float_as_uint(lz0)));
    float bz1 = __uint_as_float(__reduce_max_sync(0xffffffffu, __float_as_uint(lz1)));

    float dd[16];
#pragma unroll
    for (int i = 0; i < 16; i++) dd[i] = 1e10f;

    unsigned long long kcache = 0x7F800000ULL << 32;   // U = +inf -> first iter updates

    int far = 0;
    for (int it = 0; it < Sc; ++it) {
        float cx = sx[far], cy = sy[far], cz = sz[far];
        if (tid == 0) {
            float* o = &out_newx[((size_t)b*Sc + it)*3];
            o[0] = cx; o[1] = cy; o[2] = cz;
        }

        // conservative box-distance skip test (warp-uniform)
        float tx = fmaxf(fmaxf(bx0 - cx, cx - bx1), 0.f);
        float ty = fmaxf(fmaxf(by0 - cy, cy - by1), 0.f);
        float tz = fmaxf(fmaxf(bz0 - cz, cz - bz1), 0.f);
        float d2 = fmaf(tx, tx, fmaf(ty, ty, tz*tz));
        float U  = __uint_as_float((unsigned)(kcache >> 32));

        if (!(d2 * 0.999997f >= U)) {
            unsigned long long NX = pk2(-cx, -cx), NY = pk2(-cy, -cy), NZ = pk2(-cz, -cz);
            float m = -1.f;
#pragma unroll
            for (int k = 0; k < 8; k++)
                upd2(Xr[k], Yr[k], Zr[k], NX, NY, NZ, dd[2*k], dd[2*k+1], m);

            unsigned wmax = __reduce_max_sync(0xffffffffu, __float_as_uint(m));
            unsigned cand = 0xFFFFFFFFu;
#pragma unroll
            for (int k = 0; k < 8; k++) {
                if (__float_as_uint(dd[2*k])   == wmax) cand = min(cand, oi[k] & 0xFFFFu);
                if (__float_as_uint(dd[2*k+1]) == wmax) cand = min(cand, oi[k] >> 16);
            }
            unsigned wc = __reduce_min_sync(0xffffffffu, cand);
            kcache = ((unsigned long long)wmax << 32) | (unsigned)(Nc - 1 - wc);
        }

        unsigned long long* buf = swb + (it & 1)*16;
        if (lane == 0) buf[wid] = kcache;
        __syncthreads();

        unsigned long long e = buf[lane & 15];
        unsigned hi = (unsigned)(e >> 32);
        unsigned lo = (unsigned)(e & 0xFFFFFFFFull);
        unsigned M  = __reduce_max_sync(0xffffffffu, hi);
        unsigned r  = __reduce_max_sync(0xffffffffu, (hi == M) ? lo : 0u);
        far = Nc - 1 - (int)r;
    }
}

// ---------------- ball query + group + center + h0 moment accumulation ----------------
__global__ void ball_kernel(const float* __restrict__ x, const float* __restrict__ newx) {
    __shared__ double sm9[9];
    int tid = threadIdx.x;
    if (tid < 9) sm9[tid] = 0.0;
    __syncthreads();

    int gw   = (blockIdx.x * blockDim.x + tid) >> 5;
    int lane = tid & 31;
    int b = gw >> 10;
    const float* xb = x + (size_t)b*Nc*3;

    float cx = newx[gw*3+0], cy = newx[gw*3+1], cz = newx[gw*3+2];
    float c2 = __fadd_rn(__fadd_rn(__fmul_rn(cx,cx), __fmul_rn(cy,cy)), __fmul_rn(cz,cz));

    int cnt = 0, firstIdx = -1;
    int pb = gw * Kc;
    float m1 = 0.f, m2 = 0.f, m3 = 0.f, m4 = 0.f, m5 = 0.f, m6 = 0.f, m7 = 0.f, m8 = 0.f, m9 = 0.f;

    for (int base = 0; base < Nc && cnt < Kc; base += 32) {
        int j = base + lane;
        float ax = xb[j*3+0], ay = xb[j*3+1], az = xb[j*3+2];
        float dot = __fadd_rn(__fadd_rn(__fmul_rn(cx,ax), __fmul_rn(cy,ay)), __fmul_rn(cz,az));
        float p2  = __fadd_rn(__fadd_rn(__fmul_rn(ax,ax), __fmul_rn(ay,ay)), __fmul_rn(az,az));
        float sq  = __fadd_rn(__fadd_rn(__fmul_rn(-2.0f, dot), c2), p2);
        bool in = !(sq > 0.04f);

        unsigned m = __ballot_sync(0xffffffffu, in);
        int pos = cnt + __popc(m & ((1u << lane) - 1u));
        if (in && pos < Kc) {
            float hx = ax - cx, hy = ay - cy, hz = az - cz;
            g_h0[pb + pos]        = hx;
            g_h0[Pc + pb + pos]   = hy;
            g_h0[2*Pc + pb + pos] = hz;
            m1 += hx; m2 += hy; m3 += hz;
            m4 += hx*hx; m5 += hy*hy; m6 += hz*hz;
            m7 += hx*hy; m8 += hx*hz; m9 += hy*hz;
        }
        if (firstIdx < 0 && m) firstIdx = base + __ffs(m) - 1;
        cnt += __popc(m);
    }
    cnt = min(cnt, Kc);
    if (lane >= cnt && firstIdx >= 0) {
        float ax = xb[firstIdx*3+0], ay = xb[firstIdx*3+1], az = xb[firstIdx*3+2];
        float hx = ax - cx, hy = ay - cy, hz = az - cz;
        g_h0[pb + lane]        = hx;
        g_h0[Pc + pb + lane]   = hy;
        g_h0[2*Pc + pb + lane] = hz;
        m1 += hx; m2 += hy; m3 += hz;
        m4 += hx*hx; m5 += hy*hy; m6 += hz*hz;
        m7 += hx*hy; m8 += hx*hz; m9 += hy*hz;
    }
#pragma unroll
    for (int off = 16; off; off >>= 1) {
        m1 += __shfl_xor_sync(0xffffffffu, m1, off);
        m2 += __shfl_xor_sync(0xffffffffu, m2, off);
        m3 += __shfl_xor_sync(0xffffffffu, m3, off);
        m4 += __shfl_xor_sync(0xffffffffu, m4, off);
        m5 += __shfl_xor_sync(0xffffffffu, m5, off);
        m6 += __shfl_xor_sync(0xffffffffu, m6, off);
        m7 += __shfl_xor_sync(0xffffffffu, m7, off);
        m8 += __shfl_xor_sync(0xffffffffu, m8, off);
        m9 += __shfl_xor_sync(0xffffffffu, m9, off);
    }
    if (lane == 0) {
        atomicAdd(&sm9[0], (double)m1); atomicAdd(&sm9[1], (double)m2);
        atomicAdd(&sm9[2], (double)m3); atomicAdd(&sm9[3], (double)m4);
        atomicAdd(&sm9[4], (double)m5); atomicAdd(&sm9[5], (double)m6);
        atomicAdd(&sm9[6], (double)m7); atomicAdd(&sm9[7], (double)m8);
        atomicAdd(&sm9[8], (double)m9);
    }
    __syncthreads();
    if (tid < 9) atomicAdd(&g_m0[tid], sm9[tid]);
}

// ---------------- layer 1: 3 -> 64 ----------------
__global__ void layer1_kernel(const float* __restrict__ W, const float* __restrict__ bb) {
    __shared__ float sW[64*3], sb[64];
    int tid = threadIdx.x;
    if (tid < 192) sW[tid] = W[tid];
    if (tid < 64)  sb[tid] = bb[tid];
    __syncthreads();

    int p = blockIdx.x * 256 + tid;
    float h0 = g_h0[p], h1 = g_h0[Pc + p], h2 = g_h0[2*Pc + p];
#pragma unroll
    for (int o = 0; o < 64; o++) {
        float y = fmaf(sW[o*3+2], h2, fmaf(sW[o*3+1], h1, fmaf(sW[o*3+0], h0, sb[o])));
        g_y1[(size_t)o*Pc + p] = y;
    }
}

// ---------------- init sums ----------------
__global__ void init_sums_kernel() {
    int i = threadIdx.x;
    if (i < 3*128*2) ((double*)g_sums)[i] = 0.0;
    if (i < 9) g_m0[i] = 0.0;
}

// ---------------- finalize layer0 stats from h0 moments (analytic, f64) ----------------
__global__ void finalize0_kernel(const float* __restrict__ W, const float* __restrict__ bb,
                                 const float* __restrict__ g, const float* __restrict__ be) {
    int c = threadIdx.x;
    if (c < 64) {
        double n = (double)Pc;
        double mu0 = g_m0[0]/n, mu1 = g_m0[1]/n, mu2 = g_m0[2]/n;
        double Mxx = g_m0[3]/n, Myy = g_m0[4]/n, Mzz = g_m0[5]/n;
        double Mxy = g_m0[6]/n, Mxz = g_m0[7]/n, Myz = g_m0[8]/n;
        double w0 = (double)W[c*3+0], w1 = (double)W[c*3+1], w2 = (double)W[c*3+2];
        double bv = (double)bb[c];
        double wmu = w0*mu0 + w1*mu1 + w2*mu2;
        double mean = wmu + bv;
        double ey2 = w0*w0*Mxx + w1*w1*Myy + w2*w2*Mzz
                   + 2.0*(w0*w1*Mxy + w0*w2*Mxz + w1*w2*Myz)
                   + 2.0*bv*wmu + bv*bv;
        double var = ey2 - mean*mean;
        float invstd = (float)rsqrt(var + 1e-5);
        float scale = g[c] * invstd;
        float shift = fmaf(-(float)mean, scale, be[c]);
        g_stats[0][c][0] = scale;
        g_stats[0][c][1] = shift;
    }
}

// ---------------- per-channel sum/sumsq reduction (y2 only) ----------------
__global__ void stats_kernel() {
    int c = blockIdx.y;
    const float* yc = g_y2 + (size_t)c*Pc;

    float s = 0.f, q = 0.f;
    for (int i = blockIdx.x*blockDim.x + threadIdx.x; i < Pc; i += gridDim.x*blockDim.x) {
        float v = yc[i];
        s += v; q += v*v;
    }
    double ds = s, dq = q;
#pragma unroll
    for (int off = 16; off; off >>= 1) {
        ds += __shfl_down_sync(0xffffffffu, ds, off);
        dq += __shfl_down_sync(0xffffffffu, dq, off);
    }
    __shared__ double ssm[8], sqm[8];
    int w = threadIdx.x >> 5;
    if ((threadIdx.x & 31) == 0) { ssm[w] = ds; sqm[w] = dq; }
    __syncthreads();
    if (threadIdx.x == 0) {
        double a = 0.0, bq = 0.0;
#pragma unroll
        for (int i = 0; i < 8; i++) { a += ssm[i]; bq += sqm[i]; }
        atomicAdd(&g_sums[1][c][0], a);
        atomicAdd(&g_sums[1][c][1], bq);
    }
}

// ---------------- fold BN into scale/shift (layers 1,2) ----------------
__global__ void finalize_kernel(int layer, int C, const float* __restrict__ g, const float* __restrict__ be) {
    int c = threadIdx.x;
    if (c < C) {
        double n = (double)Pc;
        double mean = g_sums[layer][c][0] / n;
        double var  = g_sums[layer][c][1] / n - mean*mean;
        float invstd = (float)rsqrt(var + 1e-5);
        float scale = g[c] * invstd;
        float shift = fmaf(-(float)mean, scale, be[c]);
        g_stats[layer][c][0] = scale;
        g_stats[layer][c][1] = shift;
    }
}

// ---------------- layer 2: 64 -> 64 (norm+ReLU of y1 on the fly) ----------------
__global__ void layer2_kernel(const float* __restrict__ W, const float* __restrict__ bb) {
    __shared__ float sW[64*64];      // [c][o]
    __shared__ float sb[64], ssc[64], ssh[64];
    int tid = threadIdx.x;
    for (int i = tid; i < 4096; i += 256) {
        int c = i >> 6, o = i & 63;
        sW[i] = W[o*64 + c];
    }
    if (tid < 64) {
        sb[tid]  = bb[tid];
        ssc[tid] = g_stats[0][tid][0];
        ssh[tid] = g_stats[0][tid][1];
    }
    __syncthreads();

    int p = blockIdx.x * 256 + tid;
    float acc[64];
#pragma unroll
    for (int o = 0; o < 64; o++) acc[o] = sb[o];

    for (int c = 0; c < 64; c++) {
        float v = g_y1[(size_t)c*Pc + p];
        float h = fmaxf(fmaf(v, ssc[c], ssh[c]), 0.f);
        const float4* wr = (const float4*)(sW + c*64);
#pragma unroll
        for (int o4 = 0; o4 < 16; o4++) {
            float4 w = wr[o4];
            acc[o4*4+0] = fmaf(w.x, h, acc[o4*4+0]);
            acc[o4*4+1] = fmaf(w.y, h, acc[o4*4+1]);
            acc[o4*4+2] = fmaf(w.z, h, acc[o4*4+2]);
            acc[o4*4+3] = fmaf(w.w, h, acc[o4*4+3]);
        }
    }
#pragma unroll
    for (int o = 0; o < 64; o++) g_y2[(size_t)o*Pc + p] = acc[o];
}

// ---------------- layer 3 fused: 64 -> 128, per-centroid max/min + global stats ----------------
__global__ void layer3_kernel(const float* __restrict__ W, const float* __restrict__ bb) {
    int half = blockIdx.y;
    __shared__ float sW[64*64];
    __shared__ float sb[64], ssc[64], ssh[64];
    __shared__ double sSum[64], sSq[64];
    int tid = threadIdx.x, lane = tid & 31;
    for (int i = tid; i < 4096; i += 256) {
        int c = i >> 6, oo = i & 63;
        sW[i] = W[(half*64 + oo)*64 + c];
    }
    if (tid < 64) {
        sb[tid]  = bb[half*64 + tid];
        ssc[tid] = g_stats[1][tid][0];
        ssh[tid] = g_stats[1][tid][1];
        sSum[tid] = 0.0; sSq[tid] = 0.0;
    }
    __syncthreads();

    int p = blockIdx.x * 256 + tid;
    float acc[64];
#pragma unroll
    for (int o = 0; o < 64; o++) acc[o] = sb[o];

    for (int c = 0; c < 64; c++) {
        float v = g_y2[(size_t)c*Pc + p];
        float h = fmaxf(fmaf(v, ssc[c], ssh[c]), 0.f);
        const float4* wr = (const float4*)(sW + c*64);
#pragma unroll
        for (int o4 = 0; o4 < 16; o4++) {
            float4 w = wr[o4];
            acc[o4*4+0] = fmaf(w.x, h, acc[o4*4+0]);
            acc[o4*4+1] = fmaf(w.y, h, acc[o4*4+1]);
            acc[o4*4+2] = fmaf(w.z, h, acc[o4*4+2]);
            acc[o4*4+3] = fmaf(w.w, h, acc[o4*4+3]);
        }
    }

    int cent = p >> 5;
    float kmx0 = 0.f, kmx1 = 0.f, kmn0 = 0.f, kmn1 = 0.f;
    double ksm0 = 0.0, ksm1 = 0.0, ksq0 = 0.0, ksq1 = 0.0;
#pragma unroll 4
    for (int o = 0; o < 64; o++) {
        float v = acc[o];
        float mx = v, mn = v, s1 = v, s2 = v*v;
#pragma unroll
        for (int off = 16; off; off >>= 1) {
            mx = fmaxf(mx, __shfl_xor_sync(0xffffffffu, mx, off));
            mn = fminf(mn, __shfl_xor_sync(0xffffffffu, mn, off));
            s1 += __shfl_xor_sync(0xffffffffu, s1, off);
            s2 += __shfl_xor_sync(0xffffffffu, s2, off);
        }
        if (o == 2*lane)     { kmx0 = mx; kmn0 = mn; ksm0 = (double)s1; ksq0 = (double)s2; }
        if (o == 2*lane + 1) { kmx1 = mx; kmn1 = mn; ksm1 = (double)s1; ksq1 = (double)s2; }
    }
    size_t base = (size_t)cent*128 + half*64 + 2*lane;
    *(float2*)&g_max3[base] = make_float2(kmx0, kmx1);
    *(float2*)&g_min3[base] = make_float2(kmn0, kmn1);

    atomicAdd(&sSum[2*lane],   ksm0);
    atomicAdd(&sSum[2*lane+1], ksm1);
    atomicAdd(&sSq[2*lane],    ksq0);
    atomicAdd(&sSq[2*lane+1],  ksq1);
    __syncthreads();
    if (tid < 64) {
        atomicAdd(&g_sums[2][half*64 + tid][0], sSum[tid]);
        atomicAdd(&g_sums[2][half*64 + tid][1], sSq[tid]);
    }
}

// ---------------- final: affine + ReLU on pre-pooled extremes ----------------
__global__ void final_kernel(float* __restrict__ outf) {
    int bs = blockIdx.x;
    int o  = threadIdx.x;
    float sc = g_stats[2][o][0], sh = g_stats[2][o][1];
    float v = (sc >= 0.f) ? g_max3[(size_t)bs*128 + o] : g_min3[(size_t)bs*128 + o];
    outf[(size_t)bs*128 + o] = fmaxf(fmaf(v, sc, sh), 0.f);
}

// ---------------- launch ----------------
extern "C" void kernel_launch(void* const* d_in, const int* in_sizes, int n_in,
                              void* d_out, int out_size) {
    const float* x   = (const float*)d_in[0];
    const float* W1  = (const float*)d_in[1];
    const float* b1  = (const float*)d_in[2];
    const float* g1  = (const float*)d_in[3];
    const float* be1 = (const float*)d_in[4];
    const float* W2  = (const float*)d_in[5];
    const float* b2  = (const float*)d_in[6];
    const float* g2  = (const float*)d_in[7];
    const float* be2 = (const float*)d_in[8];
    const float* W3  = (const float*)d_in[9];
    const float* b3  = (const float*)d_in[10];
    const float* g3  = (const float*)d_in[11];
    const float* be3 = (const float*)d_in[12];

    float* out  = (float*)d_out;            // new_x: 8*1024*3
    float* outF = out + Bc*Sc*3;            // features: 8*1024*128

    // 3*Nc coords + Nc sorted-index ints + 2*16 u64 parity buffers
    size_t fps_smem = (size_t)(3*Nc)*sizeof(float) + (size_t)Nc*sizeof(int)
                    + 32*sizeof(unsigned long long);
    cudaFuncSetAttribute(fps_kernel, cudaFuncAttributeMaxDynamicSharedMemorySize, (int)fps_smem);

    fps_kernel<<<Bc, 512, fps_smem>>>(x, out);
    init_sums_kernel<<<1, 1024>>>();
    ball_kernel<<<(Bc*Sc*32)/256, 256>>>(x, out);

    layer1_kernel<<<Pc/256, 256>>>(W1, b1);
    finalize0_kernel<<<1, 64>>>(W1, b1, g1, be1);

    layer2_kernel<<<Pc/256, 256>>>(W2, b2);
    stats_kernel<<<dim3(64, 64), 256>>>();
    finalize_kernel<<<1, 128>>>(1, 64, g2, be2);

    layer3_kernel<<<dim3(Pc/256, 2), 256>>>(W3, b3);
    finalize_kernel<<<1, 128>>>(2, 128, g3, be3);

    final_kernel<<<Bc*Sc, 128>>>(outF);
}

// round 16
// speedup vs baseline: 1.1589x; 1.0597x over previous
#include <cuda_runtime.h>
#include <cuda_bf16.h>

#define Bc 8
#define Nc 8192
#define Sc 1024
#define Kc 32
#define Pc (Bc*Sc*Kc)   // 262144 total grouped points

// ---------------- scratch (static device globals; no allocation) ----------------
__device__ float  g_h0[3*Pc];          // centered grouped coords, [c][P]
__device__ float  g_y2[64*Pc];         // 64 MiB
__device__ float  g_max3[Bc*Sc*128];   // per-centroid per-channel max of y3 (4 MiB)
__device__ float  g_min3[Bc*Sc*128];   // per-centroid per-channel min of y3 (4 MiB)
__device__ double g_sums[3][128][2];   // per-layer per-channel (sum, sumsq)
__device__ double g_m0[9];             // h0 moments: Sx,Sy,Sz,Sxx,Syy,Szz,Sxy,Sxz,Syz
__device__ float  g_stats[3][128][2];  // per-layer per-channel (scale, shift)

// ---------------- packed f32x2 pack helper ----------------
__device__ __forceinline__ unsigned long long pk2(float lo, float hi) {
    unsigned long long r; asm("mov.b64 %0, {%1, %2};" : "=l"(r) : "f"(lo), "f"(hi)); return r;
}

// Fused per-pair FPS update: ONE asm block, all temps internal. Exact semantics
// identical to the passing R7/R9/R12 path (unfused RN ops, same order).
__device__ __forceinline__ void upd2(unsigned long long X, unsigned long long Y, unsigned long long Z,
                                     unsigned long long NX, unsigned long long NY, unsigned long long NZ,
                                     float& d0, float& d1, float& m) {
    asm("{\n\t"
        ".reg .b64 dx, dy, dz, tx, ty, tz, s;\n\t"
        ".reg .f32 lo, hi;\n\t"
        "add.rn.f32x2 dx, %3, %6;\n\t"
        "add.rn.f32x2 dy, %4, %7;\n\t"
        "add.rn.f32x2 dz, %5, %8;\n\t"
        "mul.rn.f32x2 tx, dx, dx;\n\t"
        "mul.rn.f32x2 ty, dy, dy;\n\t"
        "mul.rn.f32x2 tz, dz, dz;\n\t"
        "add.rn.f32x2 s, tx, ty;\n\t"
        "add.rn.f32x2 s, s, tz;\n\t"
        "mov.b64 {lo, hi}, s;\n\t"
        "min.f32 %0, %0, lo;\n\t"
        "min.f32 %1, %1, hi;\n\t"
        "max.f32 %2, %2, %0;\n\t"
        "max.f32 %2, %2, %1;\n\t"
        "}"
        : "+f"(d0), "+f"(d1), "+f"(m)
        : "l"(X), "l"(Y), "l"(Z), "l"(NX), "l"(NY), "l"(NZ));
}

// ---------------- FPS v7 (R12-proven): exact warp-level spatial pruning ----------------
__global__ void __launch_bounds__(512, 1)
fps_kernel(const float* __restrict__ x, float* __restrict__ out_newx) {
    extern __shared__ float sm[];
    float* sx = sm;
    float* sy = sm + Nc;
    float* sz = sm + 2*Nc;
    int*   spidx = (int*)(sm + 3*Nc);                      // sorted orig indices
    unsigned long long* swb = (unsigned long long*)(spidx + Nc);  // [2][16] parity bufs
    __shared__ int s_cnt[64];

    int b = blockIdx.x, tid = threadIdx.x;
    int lane = tid & 31, wid = tid >> 5;
    const float* xb = x + (size_t)b*Nc*3;

    for (int i = tid; i < Nc; i += 512) {
        sx[i] = xb[i*3+0];
        sy[i] = xb[i*3+1];
        sz[i] = xb[i*3+2];
    }
    if (tid < 64) s_cnt[tid] = 0;
    __syncthreads();

    // ---- counting sort by Morton cell (init only) ----
    int rank16[16]; int cid16[16];
#pragma unroll
    for (int t = 0; t < 16; t++) {
        int i = tid + t*512;
        int ix = min((int)(sx[i]*4.f), 3);
        int iy = min((int)(sy[i]*4.f), 3);
        int iz = min((int)(sz[i]*4.f), 3);
        int cid = (ix&1) | ((iy&1)<<1) | ((iz&1)<<2)
                | ((ix>>1)<<3) | ((iy>>1)<<4) | ((iz>>1)<<5);
        cid16[t] = cid;
        rank16[t] = atomicAdd(&s_cnt[cid], 1);
    }
    __syncthreads();
    if (tid == 0) {
        int acc = 0;
#pragma unroll
        for (int c = 0; c < 64; c++) { int v = s_cnt[c]; s_cnt[c] = acc; acc += v; }
    }
    __syncthreads();
#pragma unroll
    for (int t = 0; t < 16; t++)
        spidx[s_cnt[cid16[t]] + rank16[t]] = tid + t*512;
    __syncthreads();

    // ---- register load (16 pts/thread via sorted indices) + warp bbox ----
    unsigned long long Xr[8], Yr[8], Zr[8];
    unsigned oi[8];            // two 16-bit orig indices per pair
    float lx0 = 1e30f, lx1 = -1e30f, ly0 = 1e30f, ly1 = -1e30f, lz0 = 1e30f, lz1 = -1e30f;
#pragma unroll
    for (int k = 0; k < 8; k++) {
        int pos = wid*512 + k*64 + lane*2;
        int i0 = spidx[pos], i1 = spidx[pos+1];
        float x0 = sx[i0], x1 = sx[i1];
        float y0 = sy[i0], y1 = sy[i1];
        float z0 = sz[i0], z1 = sz[i1];
        Xr[k] = pk2(x0, x1); Yr[k] = pk2(y0, y1); Zr[k] = pk2(z0, z1);
        oi[k] = (unsigned)i0 | ((unsigned)i1 << 16);
        lx0 = fminf(lx0, fminf(x0, x1)); lx1 = fmaxf(lx1, fmaxf(x0, x1));
        ly0 = fminf(ly0, fminf(y0, y1)); ly1 = fmaxf(ly1, fmaxf(y0, y1));
        lz0 = fminf(lz0, fminf(z0, z1)); lz1 = fmaxf(lz1, fmaxf(z0, z1));
    }
    // coords >= 0 -> uint order == float order
    float bx0 = __uint_as_float(__reduce_min_sync(0xffffffffu, __float_as_uint(lx0)));
    float bx1 = __uint_as_float(__reduce_max_sync(0xffffffffu, __float_as_uint(lx1)));
    float by0 = __uint_as_float(__reduce_min_sync(0xffffffffu, __float_as_uint(ly0)));
    float by1 = __uint_as_float(__reduce_max_sync(0xffffffffu, __float_as_uint(ly1)));
    float bz0 = __uint_as_float(__reduce_min_sync(0xffffffffu, __float_as_uint(lz0)));
    float bz1 = __uint_as_float(__reduce_max_sync(0xffffffffu, __float_as_uint(lz1)));

    float dd[16];
#pragma unroll
    for (int i = 0; i < 16; i++) dd[i] = 1e10f;

    unsigned long long kcache = 0x7F800000ULL << 32;   // U = +inf -> first iter updates

    int far = 0;
    for (int it = 0; it < Sc; ++it) {
        float cx = sx[far], cy = sy[far], cz = sz[far];
        if (tid == 0) {
            float* o = &out_newx[((size_t)b*Sc + it)*3];
            o[0] = cx; o[1] = cy; o[2] = cz;
        }

        // conservative box-distance skip test (warp-uniform)
        float tx = fmaxf(fmaxf(bx0 - cx, cx - bx1), 0.f);
        float ty = fmaxf(fmaxf(by0 - cy, cy - by1), 0.f);
        float tz = fmaxf(fmaxf(bz0 - cz, cz - bz1), 0.f);
        float d2 = fmaf(tx, tx, fmaf(ty, ty, tz*tz));
        float U  = __uint_as_float((unsigned)(kcache >> 32));

        if (!(d2 * 0.999997f >= U)) {
            unsigned long long NX = pk2(-cx, -cx), NY = pk2(-cy, -cy), NZ = pk2(-cz, -cz);
            float m = -1.f;
#pragma unroll
            for (int k = 0; k < 8; k++)
                upd2(Xr[k], Yr[k], Zr[k], NX, NY, NZ, dd[2*k], dd[2*k+1], m);

            unsigned wmax = __reduce_max_sync(0xffffffffu, __float_as_uint(m));
            unsigned cand = 0xFFFFFFFFu;
#pragma unroll
            for (int k = 0; k < 8; k++) {
                if (__float_as_uint(dd[2*k])   == wmax) cand = min(cand, oi[k] & 0xFFFFu);
                if (__float_as_uint(dd[2*k+1]) == wmax) cand = min(cand, oi[k] >> 16);
            }
            unsigned wc = __reduce_min_sync(0xffffffffu, cand);
            kcache = ((unsigned long long)wmax << 32) | (unsigned)(Nc - 1 - wc);
        }

        unsigned long long* buf = swb + (it & 1)*16;
        if (lane == 0) buf[wid] = kcache;
        __syncthreads();

        unsigned long long e = buf[lane & 15];
        unsigned hi = (unsigned)(e >> 32);
        unsigned lo = (unsigned)(e & 0xFFFFFFFFull);
        unsigned M  = __reduce_max_sync(0xffffffffu, hi);
        unsigned r  = __reduce_max_sync(0xffffffffu, (hi == M) ? lo : 0u);
        far = Nc - 1 - (int)r;
    }
}

// ---------------- ball query + group + center + h0 moment accumulation ----------------
__global__ void ball_kernel(const float* __restrict__ x, const float* __restrict__ newx) {
    __shared__ double sm9[9];
    int tid = threadIdx.x;
    if (tid < 9) sm9[tid] = 0.0;
    __syncthreads();

    int gw   = (blockIdx.x * blockDim.x + tid) >> 5;
    int lane = tid & 31;
    int b = gw >> 10;
    const float* xb = x + (size_t)b*Nc*3;

    float cx = newx[gw*3+0], cy = newx[gw*3+1], cz = newx[gw*3+2];
    float c2 = __fadd_rn(__fadd_rn(__fmul_rn(cx,cx), __fmul_rn(cy,cy)), __fmul_rn(cz,cz));

    int cnt = 0, firstIdx = -1;
    int pb = gw * Kc;
    float m1 = 0.f, m2 = 0.f, m3 = 0.f, m4 = 0.f, m5 = 0.f, m6 = 0.f, m7 = 0.f, m8 = 0.f, m9 = 0.f;

    for (int base = 0; base < Nc && cnt < Kc; base += 32) {
        int j = base + lane;
        float ax = xb[j*3+0], ay = xb[j*3+1], az = xb[j*3+2];
        float dot = __fadd_rn(__fadd_rn(__fmul_rn(cx,ax), __fmul_rn(cy,ay)), __fmul_rn(cz,az));
        float p2  = __fadd_rn(__fadd_rn(__fmul_rn(ax,ax), __fmul_rn(ay,ay)), __fmul_rn(az,az));
        float sq  = __fadd_rn(__fadd_rn(__fmul_rn(-2.0f, dot), c2), p2);
        bool in = !(sq > 0.04f);

        unsigned m = __ballot_sync(0xffffffffu, in);
        int pos = cnt + __popc(m & ((1u << lane) - 1u));
        if (in && pos < Kc) {
            float hx = ax - cx, hy = ay - cy, hz = az - cz;
            g_h0[pb + pos]        = hx;
            g_h0[Pc + pb + pos]   = hy;
            g_h0[2*Pc + pb + pos] = hz;
            m1 += hx; m2 += hy; m3 += hz;
            m4 += hx*hx; m5 += hy*hy; m6 += hz*hz;
            m7 += hx*hy; m8 += hx*hz; m9 += hy*hz;
        }
        if (firstIdx < 0 && m) firstIdx = base + __ffs(m) - 1;
        cnt += __popc(m);
    }
    cnt = min(cnt, Kc);
    if (lane >= cnt && firstIdx >= 0) {
        float ax = xb[firstIdx*3+0], ay = xb[firstIdx*3+1], az = xb[firstIdx*3+2];
        float hx = ax - cx, hy = ay - cy, hz = az - cz;
        g_h0[pb + lane]        = hx;
        g_h0[Pc + pb + lane]   = hy;
        g_h0[2*Pc + pb + lane] = hz;
        m1 += hx; m2 += hy; m3 += hz;
        m4 += hx*hx; m5 += hy*hy; m6 += hz*hz;
        m7 += hx*hy; m8 += hx*hz; m9 += hy*hz;
    }
#pragma unroll
    for (int off = 16; off; off >>= 1) {
        m1 += __shfl_xor_sync(0xffffffffu, m1, off);
        m2 += __shfl_xor_sync(0xffffffffu, m2, off);
        m3 += __shfl_xor_sync(0xffffffffu, m3, off);
        m4 += __shfl_xor_sync(0xffffffffu, m4, off);
        m5 += __shfl_xor_sync(0xffffffffu, m5, off);
        m6 += __shfl_xor_sync(0xffffffffu, m6, off);
        m7 += __shfl_xor_sync(0xffffffffu, m7, off);
        m8 += __shfl_xor_sync(0xffffffffu, m8, off);
        m9 += __shfl_xor_sync(0xffffffffu, m9, off);
    }
    if (lane == 0) {
        atomicAdd(&sm9[0], (double)m1); atomicAdd(&sm9[1], (double)m2);
        atomicAdd(&sm9[2], (double)m3); atomicAdd(&sm9[3], (double)m4);
        atomicAdd(&sm9[4], (double)m5); atomicAdd(&sm9[5], (double)m6);
        atomicAdd(&sm9[6], (double)m7); atomicAdd(&sm9[7], (double)m8);
        atomicAdd(&sm9[8], (double)m9);
    }
    __syncthreads();
    if (tid < 9) atomicAdd(&g_m0[tid], sm9[tid]);
}

// ---------------- init sums ----------------
__global__ void init_sums_kernel() {
    int i = threadIdx.x;
    if (i < 3*128*2) ((double*)g_sums)[i] = 0.0;
    if (i < 9) g_m0[i] = 0.0;
}

// ---------------- finalize layer0 stats from h0 moments (analytic, f64) ----------------
__global__ void finalize0_kernel(const float* __restrict__ W, const float* __restrict__ bb,
                                 const float* __restrict__ g, const float* __restrict__ be) {
    int c = threadIdx.x;
    if (c < 64) {
        double n = (double)Pc;
        double mu0 = g_m0[0]/n, mu1 = g_m0[1]/n, mu2 = g_m0[2]/n;
        double Mxx = g_m0[3]/n, Myy = g_m0[4]/n, Mzz = g_m0[5]/n;
        double Mxy = g_m0[6]/n, Mxz = g_m0[7]/n, Myz = g_m0[8]/n;
        double w0 = (double)W[c*3+0], w1 = (double)W[c*3+1], w2 = (double)W[c*3+2];
        double bv = (double)bb[c];
        double wmu = w0*mu0 + w1*mu1 + w2*mu2;
        double mean = wmu + bv;
        double ey2 = w0*w0*Mxx + w1*w1*Myy + w2*w2*Mzz
                   + 2.0*(w0*w1*Mxy + w0*w2*Mxz + w1*w2*Myz)
                   + 2.0*bv*wmu + bv*bv;
        double var = ey2 - mean*mean;
        float invstd = (float)rsqrt(var + 1e-5);
        float scale = g[c] * invstd;
        float shift = fmaf(-(float)mean, scale, be[c]);
        g_stats[0][c][0] = scale;
        g_stats[0][c][1] = shift;
    }
}

// ---------------- per-channel sum/sumsq reduction (y2 only) ----------------
__global__ void stats_kernel() {
    int c = blockIdx.y;
    const float* yc = g_y2 + (size_t)c*Pc;

    float s = 0.f, q = 0.f;
    for (int i = blockIdx.x*blockDim.x + threadIdx.x; i < Pc; i += gridDim.x*blockDim.x) {
        float v = yc[i];
        s += v; q += v*v;
    }
    double ds = s, dq = q;
#pragma unroll
    for (int off = 16; off; off >>= 1) {
        ds += __shfl_down_sync(0xffffffffu, ds, off);
        dq += __shfl_down_sync(0xffffffffu, dq, off);
    }
    __shared__ double ssm[8], sqm[8];
    int w = threadIdx.x >> 5;
    if ((threadIdx.x & 31) == 0) { ssm[w] = ds; sqm[w] = dq; }
    __syncthreads();
    if (threadIdx.x == 0) {
        double a = 0.0, bq = 0.0;
#pragma unroll
        for (int i = 0; i < 8; i++) { a += ssm[i]; bq += sqm[i]; }
        atomicAdd(&g_sums[1][c][0], a);
        atomicAdd(&g_sums[1][c][1], bq);
    }
}

// ---------------- fold BN into scale/shift (layers 1,2) ----------------
__global__ void finalize_kernel(int layer, int C, const float* __restrict__ g, const float* __restrict__ be) {
    int c = threadIdx.x;
    if (c < C) {
        double n = (double)Pc;
        double mean = g_sums[layer][c][0] / n;
        double var  = g_sums[layer][c][1] / n - mean*mean;
        float invstd = (float)rsqrt(var + 1e-5);
        float scale = g[c] * invstd;
        float shift = fmaf(-(float)mean, scale, be[c]);
        g_stats[layer][c][0] = scale;
        g_stats[layer][c][1] = shift;
    }
}

// ---------------- fused layers 1+2: h0 -> y1 (registers, bit-identical) -> y2 ----------------
__global__ void layer12_kernel(const float* __restrict__ W1, const float* __restrict__ b1,
                               const float* __restrict__ W2, const float* __restrict__ b2) {
    __shared__ float sW1[64*3], sb1[64];
    __shared__ float sW2[64*64];     // [c][o]
    __shared__ float sb2[64], ssc[64], ssh[64];
    int tid = threadIdx.x;
    if (tid < 192) sW1[tid] = W1[tid];
    for (int i = tid; i < 4096; i += 256) {
        int c = i >> 6, o = i & 63;
        sW2[i] = W2[o*64 + c];
    }
    if (tid < 64) {
        sb1[tid] = b1[tid];
        sb2[tid] = b2[tid];
        ssc[tid] = g_stats[0][tid][0];
        ssh[tid] = g_stats[0][tid][1];
    }
    __syncthreads();

    int p = blockIdx.x * 256 + tid;
    float h0 = g_h0[p], h1 = g_h0[Pc + p], h2 = g_h0[2*Pc + p];

    float acc[64];
#pragma unroll
    for (int o = 0; o < 64; o++) acc[o] = sb2[o];

    for (int c = 0; c < 64; c++) {
        // y1[c] recomputed with the EXACT chain layer1 used (bit-identical)
        float y = fmaf(sW1[c*3+2], h2, fmaf(sW1[c*3+1], h1, fmaf(sW1[c*3+0], h0, sb1[c])));
        float h = fmaxf(fmaf(y, ssc[c], ssh[c]), 0.f);
        const float4* wr = (const float4*)(sW2 + c*64);
#pragma unroll
        for (int o4 = 0; o4 < 16; o4++) {
            float4 w = wr[o4];
            acc[o4*4+0] = fmaf(w.x, h, acc[o4*4+0]);
            acc[o4*4+1] = fmaf(w.y, h, acc[o4*4+1]);
            acc[o4*4+2] = fmaf(w.z, h, acc[o4*4+2]);
            acc[o4*4+3] = fmaf(w.w, h, acc[o4*4+3]);
        }
    }
#pragma unroll
    for (int o = 0; o < 64; o++) g_y2[(size_t)o*Pc + p] = acc[o];
}

// ---------------- layer 3 fused: 64 -> 128, per-centroid max/min + global stats ----------------
__global__ void layer3_kernel(const float* __restrict__ W, const float* __restrict__ bb) {
    int half = blockIdx.y;
    __shared__ float sW[64*64];
    __shared__ float sb[64], ssc[64], ssh[64];
    __shared__ double sSum[64], sSq[64];
    int tid = threadIdx.x, lane = tid & 31;
    for (int i = tid; i < 4096; i += 256) {
        int c = i >> 6, oo = i & 63;
        sW[i] = W[(half*64 + oo)*64 + c];
    }
    if (tid < 64) {
        sb[tid]  = bb[half*64 + tid];
        ssc[tid] = g_stats[1][tid][0];
        ssh[tid] = g_stats[1][tid][1];
        sSum[tid] = 0.0; sSq[tid] = 0.0;
    }
    __syncthreads();

    int p = blockIdx.x * 256 + tid;
    float acc[64];
#pragma unroll
    for (int o = 0; o < 64; o++) acc[o] = sb[o];

    for (int c = 0; c < 64; c++) {
        float v = g_y2[(size_t)c*Pc + p];
        float h = fmaxf(fmaf(v, ssc[c], ssh[c]), 0.f);
        const float4* wr = (const float4*)(sW + c*64);
#pragma unroll
        for (int o4 = 0; o4 < 16; o4++) {
            float4 w = wr[o4];
            acc[o4*4+0] = fmaf(w.x, h, acc[o4*4+0]);
            acc[o4*4+1] = fmaf(w.y, h, acc[o4*4+1]);
            acc[o4*4+2] = fmaf(w.z, h, acc[o4*4+2]);
            acc[o4*4+3] = fmaf(w.w, h, acc[o4*4+3]);
        }
    }

    int cent = p >> 5;
    float kmx0 = 0.f, kmx1 = 0.f, kmn0 = 0.f, kmn1 = 0.f;
    double ksm0 = 0.0, ksm1 = 0.0, ksq0 = 0.0, ksq1 = 0.0;
#pragma unroll 4
    for (int o = 0; o < 64; o++) {
        float v = acc[o];
        float mx = v, mn = v, s1 = v, s2 = v*v;
#pragma unroll
        for (int off = 16; off; off >>= 1) {
            mx = fmaxf(mx, __shfl_xor_sync(0xffffffffu, mx, off));
            mn = fminf(mn, __shfl_xor_sync(0xffffffffu, mn, off));
            s1 += __shfl_xor_sync(0xffffffffu, s1, off);
            s2 += __shfl_xor_sync(0xffffffffu, s2, off);
        }
        if (o == 2*lane)     { kmx0 = mx; kmn0 = mn; ksm0 = (double)s1; ksq0 = (double)s2; }
        if (o == 2*lane + 1) { kmx1 = mx; kmn1 = mn; ksm1 = (double)s1; ksq1 = (double)s2; }
    }
    size_t base = (size_t)cent*128 + half*64 + 2*lane;
    *(float2*)&g_max3[base] = make_float2(kmx0, kmx1);
    *(float2*)&g_min3[base] = make_float2(kmn0, kmn1);

    atomicAdd(&sSum[2*lane],   ksm0);
    atomicAdd(&sSum[2*lane+1], ksm1);
    atomicAdd(&sSq[2*lane],    ksq0);
    atomicAdd(&sSq[2*lane+1],  ksq1);
    __syncthreads();
    if (tid < 64) {
        atomicAdd(&g_sums[2][half*64 + tid][0], sSum[tid]);
        atomicAdd(&g_sums[2][half*64 + tid][1], sSq[tid]);
    }
}

// ---------------- final: affine + ReLU on pre-pooled extremes ----------------
__global__ void final_kernel(float* __restrict__ outf) {
    int bs = blockIdx.x;
    int o  = threadIdx.x;
    float sc = g_stats[2][o][0], sh = g_stats[2][o][1];
    float v = (sc >= 0.f) ? g_max3[(size_t)bs*128 + o] : g_min3[(size_t)bs*128 + o];
    outf[(size_t)bs*128 + o] = fmaxf(fmaf(v, sc, sh), 0.f);
}

// ---------------- launch ----------------
extern "C" void kernel_launch(void* const* d_in, const int* in_sizes, int n_in,
                              void* d_out, int out_size) {
    const float* x   = (const float*)d_in[0];
    const float* W1  = (const float*)d_in[1];
    const float* b1  = (const float*)d_in[2];
    const float* g1  = (const float*)d_in[3];
    const float* be1 = (const float*)d_in[4];
    const float* W2  = (const float*)d_in[5];
    const float* b2  = (const float*)d_in[6];
    const float* g2  = (const float*)d_in[7];
    const float* be2 = (const float*)d_in[8];
    const float* W3  = (const float*)d_in[9];
    const float* b3  = (const float*)d_in[10];
    const float* g3  = (const float*)d_in[11];
    const float* be3 = (const float*)d_in[12];

    float* out  = (float*)d_out;            // new_x: 8*1024*3
    float* outF = out + Bc*Sc*3;            // features: 8*1024*128

    // 3*Nc coords + Nc sorted-index ints + 2*16 u64 parity buffers
    size_t fps_smem = (size_t)(3*Nc)*sizeof(float) + (size_t)Nc*sizeof(int)
                    + 32*sizeof(unsigned long long);
    cudaFuncSetAttribute(fps_kernel, cudaFuncAttributeMaxDynamicSharedMemorySize, (int)fps_smem);

    fps_kernel<<<Bc, 512, fps_smem>>>(x, out);
    init_sums_kernel<<<1, 1024>>>();
    ball_kernel<<<(Bc*Sc*32)/256, 256>>>(x, out);

    finalize0_kernel<<<1, 64>>>(W1, b1, g1, be1);

    layer12_kernel<<<Pc/256, 256>>>(W1, b1, W2, b2);
    stats_kernel<<<dim3(64, 64), 256>>>();
    finalize_kernel<<<1, 128>>>(1, 64, g2, be2);

    layer3_kernel<<<dim3(Pc/256, 2), 256>>>(W3, b3);
    finalize_kernel<<<1, 128>>>(2, 128, g3, be3);

    final_kernel<<<Bc*Sc, 128>>>(outF);
}